// round 16
// baseline (speedup 1.0000x reference)
#include <cuda_runtime.h>
#include <cuda_bf16.h>
#include <cstdint>

typedef unsigned long long ull;

#define TT 512
#define BB 32
#define DD 1280
#define TBD (TT*BB*DD)
#define RNC 128
#define RTPB 256
#define NW 8
// half decomposition: 2 halves x 64 CTAs; half owns 16 batches, CTA owns 20 cols
#define GRPS 2
#define CPG 64
#define BPG 16
#define JPC 20
#define KPT 640              // k-pairs total (1280/2)
#define RSTRIDE 13           // redb per-lane float stride (odd -> conflict-free)
#define RWARP (32*RSTRIDE)   // 416 floats per warp

// smem layout: 4 W planes (Wh_hi, Wh_lo, Wx_hi, Wx_lo) as padded rows,
// 64B pad, zero row (for n-tile 2 cols 20-23), reduction buffer.
#define ROW_E 1304                      // padded row length in bf16 (2608 B)
#define ROW_B (ROW_E*2)
#define PLANE_B (JPC*ROW_B)             // 52160 B
#define ZROW_OFF (4*PLANE_B + 64)       // 64B pad -> zrow bank base 16 (conflict-free)
#define REDB_OFF (ZROW_OFF + ROW_B)
#define SMEM_REC (REDB_OFF + NW*RWARP*4)   // 224,624 B <= 227 KB

// -------- device scratch (no allocations allowed) --------
__device__ uint2 g_hb[2][GRPS][KPT*BPG];   // h bf16 split: [buf][half][kp*16+b]
__device__ unsigned g_flag[RNC*32];        // producer flags, 128B apart
__device__ float g_hlast_dummy[BB*DD];

// -------- helpers --------
__device__ __forceinline__ unsigned ld_rlx(const unsigned* p){
  unsigned v; asm volatile("ld.relaxed.gpu.global.u32 %0, [%1];" : "=r"(v) : "l"(p)); return v;
}
__device__ __forceinline__ unsigned ld_acq(const unsigned* p){
  unsigned v; asm volatile("ld.acquire.gpu.global.u32 %0, [%1];" : "=r"(v) : "l"(p)); return v;
}
__device__ __forceinline__ void st_rel(unsigned* p, unsigned v){
  asm volatile("st.release.gpu.global.u32 [%0], %1;" :: "l"(p), "r"(v) : "memory");
}
__device__ __forceinline__ uint2 ld_cg_u2(const uint2* p){
  uint2 r; asm volatile("ld.global.cg.v2.u32 {%0,%1}, [%2];" : "=r"(r.x), "=r"(r.y) : "l"(p)); return r;
}
__device__ __forceinline__ void st_cg_u2(uint2* p, uint2 v){
  asm volatile("st.global.cg.v2.u32 [%0], {%1,%2};" :: "l"(p), "r"(v.x), "r"(v.y) : "memory");
}
__device__ __forceinline__ uint32_t lds_u32(uint32_t a){
  uint32_t v; asm volatile("ld.shared.u32 %0, [%1];" : "=r"(v) : "r"(a)); return v;
}
__device__ __forceinline__ float fast_tanh(float x){
  float e = __expf(2.0f * x);
  return 1.0f - __fdividef(2.0f, e + 1.0f);
}
__device__ __forceinline__ uint32_t bf2_u32(__nv_bfloat162 v){
  uint32_t r; memcpy(&r, &v, 4); return r;
}
__device__ __forceinline__ uint32_t smem_u32(const void* p){
  return (uint32_t)__cvta_generic_to_shared(p);
}
// split a float2 (low = first elem) into bf16x2 hi + lo words
__device__ __forceinline__ void split_f2(float2 q, uint32_t& hi, uint32_t& lo){
  __nv_bfloat162 h = __floats2bfloat162_rn(q.x, q.y);
  float2 hf = __bfloat1622float2(h);
  __nv_bfloat162 l = __floats2bfloat162_rn(q.x - hf.x, q.y - hf.y);
  hi = bf2_u32(h); lo = bf2_u32(l);
}
__device__ __forceinline__ void mma_bf16(float* c, const uint32_t* a,
                                         uint32_t b0, uint32_t b1){
  asm volatile(
    "mma.sync.aligned.m16n8k16.row.col.f32.bf16.bf16.f32 "
    "{%0,%1,%2,%3}, {%4,%5,%6,%7}, {%8,%9}, {%0,%1,%2,%3};"
    : "+f"(c[0]), "+f"(c[1]), "+f"(c[2]), "+f"(c[3])
    : "r"(a[0]), "r"(a[1]), "r"(a[2]), "r"(a[3]), "r"(b0), "r"(b1));
}

// ======================================================================
// Kernel 0: reset flags + h0 -> bf16 hi/lo pair layout
// ======================================================================
__global__ void init_state(const float* __restrict__ h0)
{
  int idx = blockIdx.x * blockDim.x + threadIdx.x;
  int stride = gridDim.x * blockDim.x;
  if (idx < RNC * 32) g_flag[idx] = 0;
  for (int i = idx; i < BB * KPT; i += stride) {
    int gb = i / KPT, kp = i % KPT;
    int half = gb >> 4, b = gb & 15;
    float v0 = h0[gb * DD + 2*kp], v1 = h0[gb * DD + 2*kp + 1];
    __nv_bfloat162 hi = __floats2bfloat162_rn(v0, v1);
    __nv_bfloat162 lo = __floats2bfloat162_rn(v0 - __bfloat162float(hi.x),
                                              v1 - __bfloat162float(hi.y));
    g_hb[0][half][kp * BPG + b] = make_uint2(bf2_u32(hi), bf2_u32(lo));
  }
}

// ======================================================================
// Kernel 1: FUSED recurrence + x-projection on tensor cores.
// 2 halves x 64 CTAs; CTA: 16 batches x 20 cols, both Wh and Wx slices
// resident in smem as bf16 hi/lo padded rows (B-fragments = direct LDS.32).
// Per step: x-MMAs (no h dependency) run BEFORE the producer wait, filling
// the sync slack; h-MMAs accumulate after. Epilogue adds bias, tanh, gate.
// ======================================================================
__global__ __launch_bounds__(RTPB, 1) void recurrence(
    const float* __restrict__ xseq, const float* __restrict__ zseq,
    const float* __restrict__ Wh,   const float* __restrict__ Wx,
    const float* __restrict__ bias, float* __restrict__ out,
    float* __restrict__ hlast)
{
  extern __shared__ char sm[];
  const uint32_t smb = smem_u32(sm);
  float* redb = (float*)(sm + REDB_OFF);

  const int tid = threadIdx.x, bid = blockIdx.x;
  const int lane = tid & 31, wid = tid >> 5;
  const int half = bid >> 6;
  const int c = bid & 63;
  const int j0 = c * JPC;
  const int gb0 = half * BPG;
  const int g = lane >> 2, tg = lane & 3;

  // ---- zero row ----
  for (int i = tid; i < ROW_B/4; i += RTPB)
    ((uint32_t*)(sm + ZROW_OFF))[i] = 0;

  // ---- build W planes: [0]=Wh_hi [1]=Wh_lo [2]=Wx_hi [3]=Wx_lo ----
  for (int i = tid; i < JPC * DD; i += RTPB) {
    int j = i / DD, k = i % DD;
    float wh = Wh[(size_t)(j0 + j) * DD + k];
    float wx = Wx[(size_t)(j0 + j) * DD + k];
    __nv_bfloat16 hh = __float2bfloat16(wh);
    __nv_bfloat16 hl = __float2bfloat16(wh - __bfloat162float(hh));
    __nv_bfloat16 xh = __float2bfloat16(wx);
    __nv_bfloat16 xl = __float2bfloat16(wx - __bfloat162float(xh));
    int o = j * ROW_E + k;
    ((__nv_bfloat16*)(sm + 0*PLANE_B))[o] = hh;
    ((__nv_bfloat16*)(sm + 1*PLANE_B))[o] = hl;
    ((__nv_bfloat16*)(sm + 2*PLANE_B))[o] = xh;
    ((__nv_bfloat16*)(sm + 3*PLANE_B))[o] = xl;
  }

  // ---- epilogue pair-task mapping (unchanged from R12, verified) ----
  const bool active = (tid < BPG * JPC / 2);        // 160 threads
  const int eb = tid / (JPC/2), jp = tid % (JPC/2);
  const int jg = j0 + 2 * jp;
  const int oidx = (gb0 + eb) * DD + jg;
  const int kpg = j0 / 2 + jp;                      // GLOBAL k-pair index
  const int ent = (2 * jp) >> 3;
  const int elane = (eb & 7) * 4 + (((2 * jp) & 7) >> 1);
  const int ereg = 2 * (eb >> 3);
  const int rs0 = elane * RSTRIDE + ent * 4 + ereg;

  // ---- per-lane B-fragment base addresses: pW[plane][ntile] ----
  // word = nl*652 + ksg*8 + ltg ; ksg = wid*10 + ks -> bake in wid*320 bytes
  uint32_t pW[4][3];
  #pragma unroll
  for (int p = 0; p < 4; ++p)
    #pragma unroll
    for (int nt = 0; nt < 3; ++nt) {
      int nl = nt * 8 + (lane >> 2);
      uint32_t off = (nl < JPC) ? (uint32_t)(p * PLANE_B + nl * ROW_B)
                                : (uint32_t)ZROW_OFF;
      pW[p][nt] = smb + off + (lane & 3) * 4 + wid * 320;
    }

  __syncthreads();

  // warp w's producers: half CTAs 8w..8w+7; two quartets
  const unsigned* flagA = g_flag + (((half << 6) + (wid << 3) + (lane & 3)) << 5);
  const unsigned* flagB = g_flag + (((half << 6) + (wid << 3) + 4 + (lane & 3)) << 5);
  const int kb = wid * 80;              // warp's base k-pair (h layout)

  // per-lane x pointer: row gb0+g, k = wid*160 + 2*tg (advances by BB*DD per t)
  const float* xlane = xseq + (size_t)(gb0 + g) * DD + wid * 160 + 2 * tg;

  float2 bv = active ? *(const float2*)&bias[jg] : make_float2(0.f, 0.f);
  size_t base = 0;
  float2 zz = active ? *(const float2*)&zseq[oidx] : make_float2(0.f, 0.f);

  for (int t = 0; t < TT; ++t) {
    const uint2* hb = g_hb[t & 1][half];
    uint2*       hn = g_hb[(t & 1) ^ 1][half];

    float acc[3][4];
    #pragma unroll
    for (int nt = 0; nt < 3; ++nt)
      #pragma unroll
      for (int r = 0; r < 4; ++r) acc[nt][r] = 0.f;

    // ================= x phase (no h dependency — fills sync slack) =====
    {
      float2 X[2][4];
      auto loadX = [&](int ks, int buf) {
        const float* p = xlane + ks * 16;
        X[buf][0] = *(const float2*)p;              // [g][k0]
        X[buf][1] = *(const float2*)(p + 8 * DD);   // [g+8][k0]
        X[buf][2] = *(const float2*)(p + 8);        // [g][k0+8]
        X[buf][3] = *(const float2*)(p + 8 * DD + 8);
      };
      loadX(0, 0); loadX(1, 1);
      #pragma unroll
      for (int ks = 0; ks < 10; ++ks) {
        float2 q0 = X[ks & 1][0], q1 = X[ks & 1][1];
        float2 q2 = X[ks & 1][2], q3 = X[ks & 1][3];
        if (ks + 2 < 10) loadX(ks + 2, ks & 1);
        uint32_t Ahi[4], Alo[4];
        split_f2(q0, Ahi[0], Alo[0]); split_f2(q1, Ahi[1], Alo[1]);
        split_f2(q2, Ahi[2], Alo[2]); split_f2(q3, Ahi[3], Alo[3]);
        const uint32_t ko = ks * 32;
        #pragma unroll
        for (int nt = 0; nt < 3; ++nt) {
          uint32_t bh0 = lds_u32(pW[2][nt] + ko), bh1 = lds_u32(pW[2][nt] + ko + 16);
          uint32_t bl0 = lds_u32(pW[3][nt] + ko), bl1 = lds_u32(pW[3][nt] + ko + 16);
          mma_bf16(acc[nt], Ahi, bh0, bh1);
          mma_bf16(acc[nt], Ahi, bl0, bl1);
          mma_bf16(acc[nt], Alo, bh0, bh1);
        }
      }
    }

    // ================= h phase (producer-gated) =========================
    if (t > 0) {
      unsigned v = ld_rlx(flagA);
      while (!__all_sync(0xffffffffu, v >= (unsigned)t)) v = ld_rlx(flagA);
      ld_acq(flagA);
    }
    {
      uint2 A[2][4];
      auto loadK = [&](int ks, int buf) {
        const uint2* p = hb + (kb + 8 * ks + tg) * BPG;
        A[buf][0] = ld_cg_u2(p + g);
        A[buf][1] = ld_cg_u2(p + g + 8);
        A[buf][2] = ld_cg_u2(p + 4 * BPG + g);
        A[buf][3] = ld_cg_u2(p + 4 * BPG + g + 8);
      };
      loadK(0, 0); loadK(1, 1);
      #pragma unroll
      for (int ks = 0; ks < 10; ++ks) {
        if (ks == 3 && t > 0) {
          unsigned v = ld_rlx(flagB);
          while (!__all_sync(0xffffffffu, v >= (unsigned)t)) v = ld_rlx(flagB);
          ld_acq(flagB);
        }
        uint2 c0 = A[ks & 1][0], c1 = A[ks & 1][1];
        uint2 c2 = A[ks & 1][2], c3 = A[ks & 1][3];
        if (ks + 2 < 10) loadK(ks + 2, ks & 1);
        uint32_t Ahi[4] = {c0.x, c1.x, c2.x, c3.x};
        uint32_t Alo[4] = {c0.y, c1.y, c2.y, c3.y};
        const uint32_t ko = ks * 32;
        #pragma unroll
        for (int nt = 0; nt < 3; ++nt) {
          uint32_t bh0 = lds_u32(pW[0][nt] + ko), bh1 = lds_u32(pW[0][nt] + ko + 16);
          uint32_t bl0 = lds_u32(pW[1][nt] + ko), bl1 = lds_u32(pW[1][nt] + ko + 16);
          mma_bf16(acc[nt], Ahi, bh0, bh1);
          mma_bf16(acc[nt], Ahi, bl0, bl1);
          mma_bf16(acc[nt], Alo, bh0, bh1);
        }
      }
    }

    // ---- stage partials: redb[wid][lane][nt*4+r], conflict-free ----
    {
      float* rp = redb + wid * RWARP + lane * RSTRIDE;
      #pragma unroll
      for (int nt = 0; nt < 3; ++nt)
        #pragma unroll
        for (int r = 0; r < 4; ++r)
          rp[nt * 4 + r] = acc[nt][r];
    }
    __syncthreads();   // A: partials visible; all warps passed polls => hn overwrite safe

    // ---- critical-path epilogue: reduce, +bias, tanh, store h ----
    float hv0 = 0.f, hv1 = 0.f;
    if (active) {
      float s0 = bv.x, s1 = bv.y;
      #pragma unroll
      for (int w = 0; w < NW; ++w) {
        const float* rb = redb + w * RWARP;
        s0 += rb[rs0]; s1 += rb[rs0 + 1];
      }
      hv0 = fast_tanh(s0);
      hv1 = fast_tanh(s1);
      __nv_bfloat162 hi = __floats2bfloat162_rn(hv0, hv1);
      __nv_bfloat162 lo = __floats2bfloat162_rn(hv0 - __bfloat162float(hi.x),
                                                hv1 - __bfloat162float(hi.y));
      st_cg_u2(&hn[kpg * BPG + eb], make_uint2(bf2_u32(hi), bf2_u32(lo)));
    }
    __syncthreads();   // B: hn stores issued, redb reads done

    // ---- publish ----
    if (tid == 0) st_rel(&g_flag[bid * 32], (unsigned)(t + 1));

    // ---- off-path: silu, gated output, hlast, next-step z prefetch ----
    if (active) {
      float sz0 = __fdividef(zz.x, 1.0f + __expf(-zz.x));
      float sz1 = __fdividef(zz.y, 1.0f + __expf(-zz.y));
      *(float2*)&out[base + oidx] = make_float2(hv0 * sz0, hv1 * sz1);
      if (t == TT - 1) *(float2*)&hlast[oidx] = make_float2(hv0, hv1);
    }
    base += (size_t)BB * DD;
    xlane += (size_t)BB * DD;
    if (active && t + 1 < TT)
      zz = *(const float2*)&zseq[base + oidx];
  }
}

// ======================================================================
extern "C" void kernel_launch(void* const* d_in, const int* in_sizes, int n_in,
                              void* d_out, int out_size)
{
  const float* x    = (const float*)d_in[0];
  const float* z    = (const float*)d_in[1];
  const float* h0   = (const float*)d_in[2];
  const float* Wx   = (const float*)d_in[3];
  const float* Wh   = (const float*)d_in[4];
  const float* bias = (const float*)d_in[5];

  float* out = (float*)d_out;
  void* dummy = nullptr;
  cudaGetSymbolAddress(&dummy, g_hlast_dummy);
  float* hlast = (out_size >= (int)(TBD + BB * DD)) ? (out + TBD) : (float*)dummy;

  cudaFuncSetAttribute(recurrence, cudaFuncAttributeMaxDynamicSharedMemorySize, SMEM_REC);

  init_state<<<40, 256>>>(h0);
  recurrence<<<RNC, RTPB, SMEM_REC>>>(x, z, Wh, Wx, bias, out, hlast);
}

// round 17
// speedup vs baseline: 1.4462x; 1.4462x over previous
#include <cuda_runtime.h>
#include <cuda_bf16.h>
#include <cstdint>

typedef unsigned long long ull;

#define TT 512
#define BB 32
#define DD 1280
#define TBD (TT*BB*DD)   // 20971520
#define RNC 128
#define RTPB 256
#define NW 8
// half decomposition: 2 halves x 64 CTAs; half owns 16 batches, CTA owns 20 cols
#define GRPS 2
#define CPG 64
#define BPG 16
#define JPC 20
#define KPT 640          // k-pairs total (1280/2)
#define NFRAG 7680       // 80 ksteps * 3 ntiles * 32 lanes

// -------- device scratch (no allocations allowed) --------
__device__ float g_xp[TBD];                      // x @ Wx^T + b
__device__ uint2 g_hb[2][GRPS][KPT*BPG];         // h bf16 split: [buf][half][kp*16+b]
__device__ unsigned g_flag[RNC*32];              // producer flags, 128B apart
__device__ float g_hlast_dummy[BB*DD];
__device__ __nv_bfloat16 g_xh[TBD];
__device__ __nv_bfloat16 g_xl[TBD];
__device__ __nv_bfloat16 g_wh[DD*DD];
__device__ __nv_bfloat16 g_wl[DD*DD];

// -------- helpers --------
__device__ __forceinline__ unsigned ld_acq(const unsigned* p){
  unsigned v; asm volatile("ld.acquire.gpu.global.u32 %0, [%1];" : "=r"(v) : "l"(p)); return v;
}
__device__ __forceinline__ void st_rel(unsigned* p, unsigned v){
  asm volatile("st.release.gpu.global.u32 [%0], %1;" :: "l"(p), "r"(v) : "memory");
}
__device__ __forceinline__ uint2 ld_cg_u2(const uint2* p){
  uint2 r; asm volatile("ld.global.cg.v2.u32 {%0,%1}, [%2];" : "=r"(r.x), "=r"(r.y) : "l"(p)); return r;
}
__device__ __forceinline__ void st_cg_u2(uint2* p, uint2 v){
  asm volatile("st.global.cg.v2.u32 [%0], {%1,%2};" :: "l"(p), "r"(v.x), "r"(v.y) : "memory");
}
__device__ __forceinline__ float fast_tanh(float x){
  float e = __expf(2.0f * x);
  return 1.0f - __fdividef(2.0f, e + 1.0f);
}
__device__ __forceinline__ uint32_t bf2_u32(__nv_bfloat162 v){
  uint32_t r; memcpy(&r, &v, 4); return r;
}
__device__ __forceinline__ uint32_t smem_u32(const void* p){
  return (uint32_t)__cvta_generic_to_shared(p);
}
__device__ __forceinline__ void cp_async16(uint32_t dst, const void* src){
  asm volatile("cp.async.cg.shared.global [%0], [%1], 16;" :: "r"(dst), "l"(src));
}
__device__ __forceinline__ void cp_commit(){ asm volatile("cp.async.commit_group;" ::: "memory"); }
template<int N> __device__ __forceinline__ void cp_wait(){
  asm volatile("cp.async.wait_group %0;" :: "n"(N) : "memory");
}
__device__ __forceinline__ void ldsm_x4(uint32_t* r, uint32_t addr){
  asm volatile("ldmatrix.sync.aligned.m8n8.x4.shared.b16 {%0,%1,%2,%3}, [%4];"
    : "=r"(r[0]), "=r"(r[1]), "=r"(r[2]), "=r"(r[3]) : "r"(addr));
}
__device__ __forceinline__ void mma_bf16(float* c, const uint32_t* a,
                                         uint32_t b0, uint32_t b1){
  asm volatile(
    "mma.sync.aligned.m16n8k16.row.col.f32.bf16.bf16.f32 "
    "{%0,%1,%2,%3}, {%4,%5,%6,%7}, {%8,%9}, {%0,%1,%2,%3};"
    : "+f"(c[0]), "+f"(c[1]), "+f"(c[2]), "+f"(c[3])
    : "r"(a[0]), "r"(a[1]), "r"(a[2]), "r"(a[3]), "r"(b0), "r"(b1));
}

// ======================================================================
// Kernel A: split fp32 -> bf16 hi/lo pair (for GEMM)
// ======================================================================
__global__ void convert_split(const float* __restrict__ src,
                              __nv_bfloat16* __restrict__ hi,
                              __nv_bfloat16* __restrict__ lo, size_t n)
{
  size_t stride = (size_t)gridDim.x * blockDim.x * 4;
  for (size_t i = ((size_t)blockIdx.x * blockDim.x + threadIdx.x) * 4; i < n; i += stride) {
    float4 v = *(const float4*)(src + i);
    __nv_bfloat162 h01 = __floats2bfloat162_rn(v.x, v.y);
    __nv_bfloat162 h23 = __floats2bfloat162_rn(v.z, v.w);
    __nv_bfloat162 l01 = __floats2bfloat162_rn(v.x - __bfloat162float(h01.x),
                                               v.y - __bfloat162float(h01.y));
    __nv_bfloat162 l23 = __floats2bfloat162_rn(v.z - __bfloat162float(h23.x),
                                               v.w - __bfloat162float(h23.y));
    *(__nv_bfloat162*)(hi + i)     = h01;
    *(__nv_bfloat162*)(hi + i + 2) = h23;
    *(__nv_bfloat162*)(lo + i)     = l01;
    *(__nv_bfloat162*)(lo + i + 2) = l23;
  }
}

// ======================================================================
// Kernel B: mma.sync bf16 GEMM.
// R17: grid TRANSPOSED (x = n-tile fast, y = m-tile) so each 148-CTA
// wave touches ~15 m-tiles of X (~10MB) -> X stays L2-resident instead
// of being re-streamed from DRAM ~10x.
// ======================================================================
#define GK 32
#define NCHUNK (DD/GK)
#define LDS_ROW 40
#define TILE_B (128*LDS_ROW*2)
#define STAGE_B (4*TILE_B)

__global__ __launch_bounds__(256) void gemm_bf16(const float* __restrict__ bias)
{
  extern __shared__ char dynsm[];
  const uint32_t tb = smem_u32(dynsm);

  const int tid = threadIdx.x;
  const int wid = tid >> 5, lane = tid & 31;
  const int wm = wid & 3, wn = wid >> 2;
  const int m0 = blockIdx.y * 128;   // R17: swapped
  const int n0 = blockIdx.x * 128;   // R17: swapped

  float acc[2][8][4];
  #pragma unroll
  for (int i = 0; i < 2; i++)
    #pragma unroll
    for (int j = 0; j < 8; j++)
      #pragma unroll
      for (int q = 0; q < 4; q++) acc[i][j][q] = 0.f;

  auto load_chunk = [&](int kc, int s) {
    const int k0 = kc * GK;
    const char* srcs[4] = {
      (const char*)(g_xh + (size_t)m0 * DD + k0),
      (const char*)(g_xl + (size_t)m0 * DD + k0),
      (const char*)(g_wh + (size_t)n0 * DD + k0),
      (const char*)(g_wl + (size_t)n0 * DD + k0) };
    #pragma unroll
    for (int tl = 0; tl < 4; ++tl) {
      uint32_t base = tb + s * STAGE_B + tl * TILE_B;
      const char* sp = srcs[tl];
      #pragma unroll
      for (int it = 0; it < 2; ++it) {
        int idx = tid + it * 256;
        int row = idx >> 2, c = idx & 3;
        cp_async16(base + row * (LDS_ROW * 2) + c * 16,
                   sp + (size_t)row * (DD * 2) + c * 16);
      }
    }
    cp_commit();
  };

  auto addrA = [&](int tile_off, int s, int row0, int ks) -> uint32_t {
    int row = row0 + (lane & 15);
    int col = ks + ((lane >> 4) << 3);
    return tb + s * STAGE_B + tile_off + (row * LDS_ROW + col) * 2;
  };
  auto addrB = [&](int tile_off, int s, int nrow0, int ks) -> uint32_t {
    int row = nrow0 + ((lane >> 4) << 3) + (lane & 7);
    int col = ks + (((lane >> 3) & 1) << 3);
    return tb + s * STAGE_B + tile_off + (row * LDS_ROW + col) * 2;
  };

  load_chunk(0, 0);
  load_chunk(1, 1);

  for (int kc = 0; kc < NCHUNK; ++kc) {
    const int s = kc & 1;
    if (kc >= NCHUNK - 2) cp_wait<0>(); else cp_wait<1>();
    __syncthreads();

    #pragma unroll
    for (int ks = 0; ks < GK; ks += 16) {
      uint32_t ah[2][4], al[2][4];
      #pragma unroll
      for (int mi = 0; mi < 2; ++mi) {
        ldsm_x4(ah[mi], addrA(0,        s, wm * 32 + mi * 16, ks));
        ldsm_x4(al[mi], addrA(TILE_B,   s, wm * 32 + mi * 16, ks));
      }
      #pragma unroll
      for (int nb = 0; nb < 4; ++nb) {
        uint32_t bh[4], bl[4];
        ldsm_x4(bh, addrB(2 * TILE_B, s, wn * 64 + nb * 16, ks));
        ldsm_x4(bl, addrB(3 * TILE_B, s, wn * 64 + nb * 16, ks));
        #pragma unroll
        for (int mi = 0; mi < 2; ++mi) {
          float* c0 = acc[mi][nb * 2];
          float* c1 = acc[mi][nb * 2 + 1];
          mma_bf16(c0, ah[mi], bh[0], bh[1]);
          mma_bf16(c1, ah[mi], bh[2], bh[3]);
          mma_bf16(c0, ah[mi], bl[0], bl[1]);
          mma_bf16(c1, ah[mi], bl[2], bl[3]);
          mma_bf16(c0, al[mi], bh[0], bh[1]);
          mma_bf16(c1, al[mi], bh[2], bh[3]);
        }
      }
    }
    __syncthreads();
    if (kc + 2 < NCHUNK) load_chunk(kc + 2, s);
  }

  const int mrow = lane >> 2, ncol = (lane & 3) * 2;
  #pragma unroll
  for (int mi = 0; mi < 2; ++mi) {
    #pragma unroll
    for (int ni = 0; ni < 8; ++ni) {
      int m = m0 + wm * 32 + mi * 16 + mrow;
      int n = n0 + wn * 64 + ni * 8 + ncol;
      float b0 = bias[n], b1 = bias[n + 1];
      *(float2*)&g_xp[(size_t)m * DD + n] =
          make_float2(acc[mi][ni][0] + b0, acc[mi][ni][1] + b1);
      *(float2*)&g_xp[(size_t)(m + 8) * DD + n] =
          make_float2(acc[mi][ni][2] + b0, acc[mi][ni][3] + b1);
    }
  }
}

// ======================================================================
// Kernel 0: reset flags + h0 -> bf16 hi/lo pair layout
// ======================================================================
__global__ void init_state(const float* __restrict__ h0)
{
  int idx = blockIdx.x * blockDim.x + threadIdx.x;
  int stride = gridDim.x * blockDim.x;
  if (idx < RNC * 32) g_flag[idx] = 0;
  for (int i = idx; i < BB * KPT; i += stride) {
    int gb = i / KPT, kp = i % KPT;
    int half = gb >> 4, b = gb & 15;
    float v0 = h0[gb * DD + 2*kp], v1 = h0[gb * DD + 2*kp + 1];
    __nv_bfloat162 hi = __floats2bfloat162_rn(v0, v1);
    __nv_bfloat162 lo = __floats2bfloat162_rn(v0 - __bfloat162float(hi.x),
                                              v1 - __bfloat162float(hi.y));
    g_hb[0][half][kp * BPG + b] = make_uint2(bf2_u32(hi), bf2_u32(lo));
  }
}

// ======================================================================
// Kernel 2: tensor-core recurrence (verbatim R12 — best measured 2263us).
// ======================================================================
__global__ __launch_bounds__(RTPB, 1) void recurrence(
    const float* __restrict__ zseq, const float* __restrict__ Wh,
    float* __restrict__ out, float* __restrict__ hlast)
{
  extern __shared__ char sm[];
  uint4* wfrag = (uint4*)sm;                       // [NFRAG] = 122880 B
  float* redb  = (float*)(sm + NFRAG * 16);        // [wid][lane][12] = 12288 B

  const int tid = threadIdx.x, bid = blockIdx.x;
  const int lane = tid & 31, wid = tid >> 5;
  const int half = bid >> 6;            // 0..1
  const int c = bid & 63;               // CTA within half
  const int j0 = c * JPC;               // absolute column base
  const int gb0 = half * BPG;           // absolute batch base
  const int g = lane >> 2, tg = lane & 3;

  // ---- build W B-fragments (hi/lo) in smem, one-time ----
  for (int idx = tid; idx < NFRAG; idx += RTPB) {
    int ksg = idx / 96;                 // global k-step 0..79 (k = 16*ksg)
    int rem = idx % 96;
    int nt = rem >> 5, l = rem & 31;
    int lg = l >> 2, ltg = l & 3;
    int nl = nt * 8 + lg;               // local col 0..23
    uint32_t b0h = 0, b1h = 0, b0l = 0, b1l = 0;
    if (nl < JPC) {
      const float* wr = Wh + (size_t)(j0 + nl) * DD + ksg * 16 + 2 * ltg;
      float w0 = wr[0], w1 = wr[1], w8 = wr[8], w9 = wr[9];
      __nv_bfloat162 h01 = __floats2bfloat162_rn(w0, w1);
      __nv_bfloat162 h89 = __floats2bfloat162_rn(w8, w9);
      __nv_bfloat162 l01 = __floats2bfloat162_rn(w0 - __bfloat162float(h01.x),
                                                 w1 - __bfloat162float(h01.y));
      __nv_bfloat162 l89 = __floats2bfloat162_rn(w8 - __bfloat162float(h89.x),
                                                 w9 - __bfloat162float(h89.y));
      b0h = bf2_u32(h01); b1h = bf2_u32(h89);
      b0l = bf2_u32(l01); b1l = bf2_u32(l89);
    }
    wfrag[idx] = make_uint4(b0h, b1h, b0l, b1l);
  }

  // ---- epilogue pair-task mapping: 160 tasks (b, col-pair) ----
  const bool active = (tid < BPG * JPC / 2);       // 160 threads
  const int eb = tid / (JPC/2), jp = tid % (JPC/2);  // batch 0..15, pair 0..9
  const int jg = j0 + 2 * jp;                       // global even column
  const int oidx = (gb0 + eb) * DD + jg;            // out/xp/z offset (float2)
  const int kpg = j0 / 2 + jp;                      // GLOBAL k-pair index
  const int ent = (2 * jp) >> 3;
  const int elane = (eb & 7) * 4 + (((2 * jp) & 7) >> 1);
  const int ereg = 2 * (eb >> 3);
  const int rs0 = elane * 12 + ent * 4 + ereg;      // col jg ; rs0+1 = col jg+1

  __syncthreads();

  // warp w's producers: half CTAs 8w..8w+7 (kp span [80w, 80w+80))
  const unsigned* myflag = g_flag + (((half << 6) + (wid << 3) + (lane & 7)) << 5);
  const int kb = wid * 80;              // warp's base k-pair

  size_t base = 0;
  float2 xp = active ? *(const float2*)&g_xp[oidx] : make_float2(0.f, 0.f);
  float2 zz = active ? *(const float2*)&zseq[oidx] : make_float2(0.f, 0.f);

  for (int t = 0; t < TT; ++t) {
    const uint2* hb = g_hb[t & 1][half];
    uint2*       hn = g_hb[(t & 1) ^ 1][half];
    float sz0 = __fdividef(zz.x, 1.0f + __expf(-zz.x));
    float sz1 = __fdividef(zz.y, 1.0f + __expf(-zz.y));

    // ---- per-warp dataflow wait: my 8 producers have written h_t ----
    if (t > 0) {
      while (true) {
        unsigned v = ld_acq(myflag);
        if (__all_sync(0xffffffffu, v >= (unsigned)t)) break;
        __nanosleep(32);
      }
    }

    // ---- tensor-core partials: 10 k-steps x 3 n-tiles x 3 split-products ----
    float acc[3][4];
    #pragma unroll
    for (int nt = 0; nt < 3; ++nt)
      #pragma unroll
      for (int r = 0; r < 4; ++r) acc[nt][r] = 0.f;

    uint2 a0, a1, a2, a3, n0, n1, n2, n3;
    {
      const uint2* p = hb + (kb + tg) * BPG;
      a0 = ld_cg_u2(p + g);  a1 = ld_cg_u2(p + g + 8);
      a2 = ld_cg_u2(p + 4 * BPG + g); a3 = ld_cg_u2(p + 4 * BPG + g + 8);
    }
    #pragma unroll
    for (int ks = 0; ks < 10; ++ks) {
      if (ks + 1 < 10) {
        const uint2* p = hb + (kb + 8 * (ks + 1) + tg) * BPG;
        n0 = ld_cg_u2(p + g);  n1 = ld_cg_u2(p + g + 8);
        n2 = ld_cg_u2(p + 4 * BPG + g); n3 = ld_cg_u2(p + 4 * BPG + g + 8);
      }
      uint32_t Ahi[4] = {a0.x, a1.x, a2.x, a3.x};
      uint32_t Alo[4] = {a0.y, a1.y, a2.y, a3.y};
      const uint4* wf = wfrag + ((wid * 10 + ks) * 3) * 32 + lane;
      uint4 w0 = wf[0], w1 = wf[32], w2 = wf[64];
      mma_bf16(acc[0], Ahi, w0.x, w0.y);
      mma_bf16(acc[1], Ahi, w1.x, w1.y);
      mma_bf16(acc[2], Ahi, w2.x, w2.y);
      mma_bf16(acc[0], Ahi, w0.z, w0.w);
      mma_bf16(acc[1], Ahi, w1.z, w1.w);
      mma_bf16(acc[2], Ahi, w2.z, w2.w);
      mma_bf16(acc[0], Alo, w0.x, w0.y);
      mma_bf16(acc[1], Alo, w1.x, w1.y);
      mma_bf16(acc[2], Alo, w2.x, w2.y);
      a0 = n0; a1 = n1; a2 = n2; a3 = n3;
    }

    // ---- stage partials: redb[wid][lane][nt*4+r] ----
    {
      float* rp = redb + wid * 384 + lane * 12;
      #pragma unroll
      for (int nt = 0; nt < 3; ++nt)
        *(float4*)(rp + nt * 4) = make_float4(acc[nt][0], acc[nt][1],
                                              acc[nt][2], acc[nt][3]);
    }
    __syncthreads();   // A: partials visible; all warps passed polls => hn overwrite safe

    // ---- epilogue: reduce 8 warps, tanh, split h to bf16 pair, store ----
    float hv0 = 0.f, hv1 = 0.f;
    if (active) {
      float s0 = 0.f, s1 = 0.f;
      #pragma unroll
      for (int w = 0; w < NW; ++w) {
        const float* rb = redb + w * 384;
        s0 += rb[rs0]; s1 += rb[rs0 + 1];
      }
      hv0 = fast_tanh(xp.x + s0);
      hv1 = fast_tanh(xp.y + s1);
      __nv_bfloat162 hi = __floats2bfloat162_rn(hv0, hv1);
      __nv_bfloat162 lo = __floats2bfloat162_rn(hv0 - __bfloat162float(hi.x),
                                                hv1 - __bfloat162float(hi.y));
      st_cg_u2(&hn[kpg * BPG + eb], make_uint2(bf2_u32(hi), bf2_u32(lo)));
    }
    __syncthreads();   // B: hn stores issued, redb reads done

    // ---- publish ----
    if (tid == 0) st_rel(&g_flag[bid * 32], (unsigned)(t + 1));

    // ---- off-path: gated output, hlast, next-step prefetch ----
    if (active) {
      *(float2*)&out[base + oidx] = make_float2(hv0 * sz0, hv1 * sz1);
      if (t == TT - 1) *(float2*)&hlast[oidx] = make_float2(hv0, hv1);
    }
    base += (size_t)BB * DD;
    if (active && t + 1 < TT) {
      xp = *(const float2*)&g_xp[base + oidx];
      zz = *(const float2*)&zseq[base + oidx];
    }
  }
}

// ======================================================================
extern "C" void kernel_launch(void* const* d_in, const int* in_sizes, int n_in,
                              void* d_out, int out_size)
{
  const float* x    = (const float*)d_in[0];
  const float* z    = (const float*)d_in[1];
  const float* h0   = (const float*)d_in[2];
  const float* Wx   = (const float*)d_in[3];
  const float* Wh   = (const float*)d_in[4];
  const float* bias = (const float*)d_in[5];

  float* out = (float*)d_out;
  void* dummy = nullptr;
  cudaGetSymbolAddress(&dummy, g_hlast_dummy);
  float* hlast = (out_size >= (int)(TBD + BB * DD)) ? (out + TBD) : (float*)dummy;

  void *p_xh, *p_xl, *p_wh, *p_wl;
  cudaGetSymbolAddress(&p_xh, g_xh); cudaGetSymbolAddress(&p_xl, g_xl);
  cudaGetSymbolAddress(&p_wh, g_wh); cudaGetSymbolAddress(&p_wl, g_wl);

  const int rec_smem  = NFRAG * 16 + NW * 384 * (int)sizeof(float);  // 135168 B
  const int gemm_smem = 2 * STAGE_B;
  cudaFuncSetAttribute(recurrence, cudaFuncAttributeMaxDynamicSharedMemorySize, rec_smem);
  cudaFuncSetAttribute(gemm_bf16,  cudaFuncAttributeMaxDynamicSharedMemorySize, gemm_smem);

  init_state<<<40, 256>>>(h0);
  convert_split<<<2048, 256>>>(x,  (__nv_bfloat16*)p_xh, (__nv_bfloat16*)p_xl, (size_t)TBD);
  convert_split<<<512, 256>>>(Wx, (__nv_bfloat16*)p_wh, (__nv_bfloat16*)p_wl, (size_t)DD*DD);
  gemm_bf16<<<dim3(10, 128), 256, gemm_smem>>>(bias);   // R17: transposed grid
  recurrence<<<RNC, RTPB, rec_smem>>>(z, Wh, out, hlast);
}